// round 1
// baseline (speedup 1.0000x reference)
#include <cuda_runtime.h>
#include <cstdint>

// Problem constants
#define B_   64
#define N_   100
#define D_   2048
#define NR_  16
#define DK_  64
#define DV_  128
#define P_   (B_*N_)          // 6400
#define KQ_COLS (NR_*DK_)     // 1024
#define PAIRS (B_*N_*N_)      // 640000

// Scratch (device globals; allocation APIs are forbidden)
__device__ float g_K[P_ * KQ_COLS];          // 6400 x 1024
__device__ float g_Q[P_ * KQ_COLS];          // 6400 x 1024
__device__ float g_gwT[B_ * NR_ * N_ * N_];  // [b][h][i*100+j]

// ---------------------------------------------------------------------------
// Kernel 1: gate  gw[b,h,i,j] = max(g_row . W_g[:,h] + b_g[h], 1e-6)
// stored transposed: g_gwT[b*160000 + h*10000 + (i*100+j)]
// ---------------------------------------------------------------------------
__global__ __launch_bounds__(256) void gate_kernel(
    const float* __restrict__ G,    // [640000, 64]
    const float* __restrict__ Wg,   // [64, 16]
    const float* __restrict__ bg,   // [16]
    float* __restrict__ out)
{
    __shared__ float sW[64][17];
    __shared__ float sb[16];
    int tid = threadIdx.x;
    if (tid < 16) sb[tid] = bg[tid];
    for (int idx = tid; idx < 64 * 16; idx += 256)
        sW[idx >> 4][idx & 15] = Wg[idx];
    __syncthreads();

    int p = blockIdx.x * 256 + tid;            // pair index 0..639999 (grid exact)
    const float4* g4 = (const float4*)(G + (size_t)p * 64);

    float acc[16];
#pragma unroll
    for (int h = 0; h < 16; h++) acc[h] = sb[h];

#pragma unroll
    for (int k4 = 0; k4 < 16; k4++) {
        float4 gv = g4[k4];
#pragma unroll
        for (int h = 0; h < 16; h++) {
            acc[h] += gv.x * sW[4 * k4 + 0][h];
            acc[h] += gv.y * sW[4 * k4 + 1][h];
            acc[h] += gv.z * sW[4 * k4 + 2][h];
            acc[h] += gv.w * sW[4 * k4 + 3][h];
        }
    }

    int b  = p / (N_ * N_);
    int lp = p - b * (N_ * N_);
    float* ob = out + (size_t)b * (NR_ * N_ * N_) + lp;
#pragma unroll
    for (int h = 0; h < 16; h++)
        ob[(size_t)h * (N_ * N_)] = fmaxf(acc[h], 1e-6f);
}

// ---------------------------------------------------------------------------
// Kernel 2: fused K/Q SGEMM.  C = A[6400,2048] @ W[2048,1024] + bias
// blockIdx.z = 0 -> K (W_K,b_K), 1 -> Q (W_Q,b_Q)
// 128x128x16 tile, 8x8 per thread, 256 threads.
// ---------------------------------------------------------------------------
__global__ __launch_bounds__(256) void sgemm_kq(
    const float* __restrict__ A,
    const float* __restrict__ Wk, const float* __restrict__ bk,
    const float* __restrict__ Wq, const float* __restrict__ bq)
{
    const float* W; const float* bias; float* C;
    if (blockIdx.z == 0) { W = Wk; bias = bk; C = g_K; }
    else                 { W = Wq; bias = bq; C = g_Q; }

    __shared__ float As[16][132];   // [k][m], padded (132*4B = 16B aligned)
    __shared__ float Bs[16][128];   // [k][n]

    int tid = threadIdx.x;
    int m0 = blockIdx.y * 128;
    int n0 = blockIdx.x * 128;
    int tm = (tid >> 4) * 8;
    int tn = (tid & 15) * 8;

    float acc[8][8];
#pragma unroll
    for (int i = 0; i < 8; i++)
#pragma unroll
        for (int j = 0; j < 8; j++) acc[i][j] = 0.f;

    for (int k0 = 0; k0 < 2048; k0 += 16) {
        // A tile: 128 rows x 16 cols
#pragma unroll
        for (int l = 0; l < 2; l++) {
            int s   = tid + l * 256;       // 0..511
            int row = s >> 2;
            int cg  = (s & 3) * 4;
            float4 v = *(const float4*)&A[(size_t)(m0 + row) * 2048 + k0 + cg];
            As[cg + 0][row] = v.x;
            As[cg + 1][row] = v.y;
            As[cg + 2][row] = v.z;
            As[cg + 3][row] = v.w;
        }
        // B tile: 16 rows x 128 cols
#pragma unroll
        for (int l = 0; l < 2; l++) {
            int s   = tid + l * 256;
            int row = s >> 5;
            int cg  = (s & 31) * 4;
            *(float4*)&Bs[row][cg] = *(const float4*)&W[(size_t)(k0 + row) * 1024 + n0 + cg];
        }
        __syncthreads();

#pragma unroll
        for (int k = 0; k < 16; k++) {
            float4 a0 = *(float4*)&As[k][tm];
            float4 a1 = *(float4*)&As[k][tm + 4];
            float4 b0 = *(float4*)&Bs[k][tn];
            float4 b1 = *(float4*)&Bs[k][tn + 4];
            float av[8] = {a0.x, a0.y, a0.z, a0.w, a1.x, a1.y, a1.z, a1.w};
            float bv[8] = {b0.x, b0.y, b0.z, b0.w, b1.x, b1.y, b1.z, b1.w};
#pragma unroll
            for (int i = 0; i < 8; i++)
#pragma unroll
                for (int j = 0; j < 8; j++)
                    acc[i][j] += av[i] * bv[j];
        }
        __syncthreads();
    }

#pragma unroll
    for (int i = 0; i < 8; i++) {
        float* crow = C + (size_t)(m0 + tm + i) * 1024 + n0 + tn;
#pragma unroll
        for (int j = 0; j < 8; j++)
            crow[j] = acc[i][j] + bias[n0 + tn + j];
    }
}

// ---------------------------------------------------------------------------
// Kernel 3: per (b,h) attention:
//   e[i][j]  = gw[b,h,i,j] * exp(k_i . q_j / 8)
//   fin[i][j] = e / sum_i e         (softmax over i, shift not needed)
//   out[b*100+j, h*128+d] = (sum_i V[i][d]*fin[i][j]) * w_s + b_s
// ---------------------------------------------------------------------------
#define KQPAD 65
#define FINPAD 112

__global__ __launch_bounds__(256) void attn_kernel(
    const float* __restrict__ Kmat,
    const float* __restrict__ Qmat,
    const float* __restrict__ gw,
    const float* __restrict__ A,      // a_features (V source)
    const float* __restrict__ wsp,
    const float* __restrict__ bsp,
    float* __restrict__ out)
{
    extern __shared__ float sm[];
    float* Ks  = sm;                      // 112 x 65
    float* Qs  = sm + 112 * KQPAD;        // 112 x 65
    float* Vs  = sm;                      // union with Ks/Qs: 100 x 128 = 12800 <= 14560
    float* fin = sm + 2 * 112 * KQPAD;    // 100 x 112
    float* csum = fin + 100 * FINPAD;     // 100 (reciprocal sums)

    int h = blockIdx.x;
    int b = blockIdx.y;
    int tid = threadIdx.x;
    int tx = tid & 15, ty = tid >> 4;

    // Phase 1: load K,Q tiles (zero-pad rows 100..111)
    for (int idx = tid; idx < 112 * 64; idx += 256) {
        int i = idx >> 6, d = idx & 63;
        float kv = 0.f, qv = 0.f;
        if (i < 100) {
            size_t g = (size_t)(b * 100 + i) * 1024 + h * 64 + d;
            kv = Kmat[g];
            qv = Qmat[g];
        }
        Ks[i * KQPAD + d] = kv;
        Qs[i * KQPAD + d] = qv;
    }
    __syncthreads();

    // Phase 2: logits -> e values
    const float* gwb = gw + ((size_t)(b * 16 + h)) * 10000;
    {
        float acc[7][7];
#pragma unroll
        for (int ii = 0; ii < 7; ii++)
#pragma unroll
            for (int jj = 0; jj < 7; jj++) acc[ii][jj] = 0.f;

        for (int d = 0; d < 64; d++) {
            float kk[7], qq[7];
#pragma unroll
            for (int ii = 0; ii < 7; ii++) kk[ii] = Ks[(ty + 16 * ii) * KQPAD + d];
#pragma unroll
            for (int jj = 0; jj < 7; jj++) qq[jj] = Qs[(tx + 16 * jj) * KQPAD + d];
#pragma unroll
            for (int ii = 0; ii < 7; ii++)
#pragma unroll
                for (int jj = 0; jj < 7; jj++)
                    acc[ii][jj] += kk[ii] * qq[jj];
        }
#pragma unroll
        for (int ii = 0; ii < 7; ii++) {
            int i = ty + 16 * ii;
            if (i >= 100) continue;
#pragma unroll
            for (int jj = 0; jj < 7; jj++) {
                int j = tx + 16 * jj;
                if (j >= 100) continue;
                float e = gwb[i * 100 + j] * __expf(acc[ii][jj] * 0.125f);
                fin[i * FINPAD + j] = e;
            }
        }
    }
    __syncthreads();

    // Phase 3a: column sums (over i) -> reciprocal; Phase 3b: load V (reuses K/Q smem)
    if (tid < 100) {
        float s = 0.f;
        for (int i = 0; i < 100; i++) s += fin[i * FINPAD + tid];
        csum[tid] = 1.f / s;
    }
    for (int idx = tid; idx < 100 * 128; idx += 256) {
        int i = idx >> 7, d = idx & 127;
        Vs[idx] = A[(size_t)(b * 100 + i) * 2048 + h * 128 + d];
    }
    __syncthreads();

    // Phase 4: AV + normalize + scalar affine
    float ws = wsp[0], bs = bsp[0];
    float r[7][8];
#pragma unroll
    for (int jj = 0; jj < 7; jj++)
#pragma unroll
        for (int dd = 0; dd < 8; dd++) r[jj][dd] = 0.f;

    for (int i = 0; i < 100; i++) {
        float vv[8], ff[7];
#pragma unroll
        for (int dd = 0; dd < 8; dd++) vv[dd] = Vs[i * 128 + tx + 16 * dd];
#pragma unroll
        for (int jj = 0; jj < 7; jj++) ff[jj] = fin[i * FINPAD + ty + 16 * jj];
#pragma unroll
        for (int jj = 0; jj < 7; jj++)
#pragma unroll
            for (int dd = 0; dd < 8; dd++)
                r[jj][dd] += vv[dd] * ff[jj];
    }

#pragma unroll
    for (int jj = 0; jj < 7; jj++) {
        int j = ty + 16 * jj;
        if (j >= 100) continue;
        float rc = csum[j];
        float* orow = out + (size_t)(b * 100 + j) * 2048 + h * 128;
#pragma unroll
        for (int dd = 0; dd < 8; dd++) {
            int d = tx + 16 * dd;
            orow[d] = (r[jj][dd] * rc) * ws + bs;
        }
    }
}

// ---------------------------------------------------------------------------
// Launcher
// Inputs (metadata order):
// 0 a_features [6400,2048] f32   1 g_features [640000,64] f32
// 2 split (i64, unused)          3 rel_pair_counts (i64, unused)
// 4 W_g [64,16]  5 b_g [16]  6 W_K [2048,1024]  7 b_K [1024]
// 8 W_Q [2048,1024]  9 b_Q [1024]  10 w_s []  11 b_s []
// ---------------------------------------------------------------------------
extern "C" void kernel_launch(void* const* d_in, const int* in_sizes, int n_in,
                              void* d_out, int out_size)
{
    const float* a_feat = (const float*)d_in[0];
    const float* g_feat = (const float*)d_in[1];
    const float* W_g    = (const float*)d_in[4];
    const float* b_g    = (const float*)d_in[5];
    const float* W_K    = (const float*)d_in[6];
    const float* b_K    = (const float*)d_in[7];
    const float* W_Q    = (const float*)d_in[8];
    const float* b_Q    = (const float*)d_in[9];
    const float* w_s    = (const float*)d_in[10];
    const float* b_s    = (const float*)d_in[11];
    float* out          = (float*)d_out;

    float *Kp, *Qp, *gwp;
    cudaGetSymbolAddress((void**)&Kp,  g_K);
    cudaGetSymbolAddress((void**)&Qp,  g_Q);
    cudaGetSymbolAddress((void**)&gwp, g_gwT);

    // 1) gate
    gate_kernel<<<PAIRS / 256, 256>>>(g_feat, W_g, b_g, gwp);

    // 2) K & Q GEMMs
    dim3 ggrid(KQ_COLS / 128, P_ / 128, 2);   // (8, 50, 2)
    sgemm_kq<<<ggrid, 256>>>(a_feat, W_K, b_K, W_Q, b_Q);

    // 3) attention + AV + affine
    int smem_bytes = (2 * 112 * KQPAD + 100 * FINPAD + 100) * (int)sizeof(float);
    cudaFuncSetAttribute(attn_kernel, cudaFuncAttributeMaxDynamicSharedMemorySize,
                         smem_bytes);
    dim3 agrid(NR_, B_);
    attn_kernel<<<agrid, 256, smem_bytes>>>(Kp, Qp, gwp, a_feat, w_s, b_s, out);
}

// round 3
// speedup vs baseline: 2.0152x; 2.0152x over previous
#include <cuda_runtime.h>
#include <cuda_bf16.h>
#include <cstdint>

// Problem constants
#define B_   64
#define N_   100
#define D_   2048
#define NR_  16
#define DK_  64
#define DV_  128
#define P_   (B_*N_)          // 6400
#define KQ_COLS (NR_*DK_)     // 1024
#define PAIRS (B_*N_*N_)      // 640000

// ---------------------------------------------------------------------------
// Scratch (device globals; allocation APIs are forbidden)
// ---------------------------------------------------------------------------
__device__ float g_K[P_ * KQ_COLS];          // 6400 x 1024
__device__ float g_Q[P_ * KQ_COLS];          // 6400 x 1024
__device__ float g_gwT[B_ * NR_ * N_ * N_];  // [b][h][i*100+j]

__device__ __align__(16) __nv_bfloat16 g_Ahi[P_ * D_];        // [m][k]
__device__ __align__(16) __nv_bfloat16 g_Alo[P_ * D_];
__device__ __align__(16) __nv_bfloat16 g_WKhi[D_ * KQ_COLS];  // [k][n]
__device__ __align__(16) __nv_bfloat16 g_WKlo[D_ * KQ_COLS];
__device__ __align__(16) __nv_bfloat16 g_WQhi[D_ * KQ_COLS];
__device__ __align__(16) __nv_bfloat16 g_WQlo[D_ * KQ_COLS];

// ---------------------------------------------------------------------------
// PTX helpers (baseline ISA only: cp.async / ldmatrix / mma.sync)
// ---------------------------------------------------------------------------
__device__ __forceinline__ uint32_t smem_u32(const void* p) {
    uint32_t a;
    asm("{ .reg .u64 t; cvta.to.shared.u64 t, %1; cvt.u32.u64 %0, t; }"
        : "=r"(a) : "l"(p));
    return a;
}
__device__ __forceinline__ void cp_async16(uint32_t dst, const void* src) {
    asm volatile("cp.async.cg.shared.global [%0], [%1], 16;" :: "r"(dst), "l"(src));
}
#define CP_COMMIT() asm volatile("cp.async.commit_group;" ::: "memory")
#define CP_WAIT(n)  asm volatile("cp.async.wait_group %0;" :: "n"(n) : "memory")

__device__ __forceinline__ void ldsm_x4(uint32_t addr, uint32_t* f) {
    asm volatile("ldmatrix.sync.aligned.m8n8.x4.shared.b16 {%0,%1,%2,%3}, [%4];"
                 : "=r"(f[0]), "=r"(f[1]), "=r"(f[2]), "=r"(f[3]) : "r"(addr));
}
__device__ __forceinline__ void ldsm_x2t(uint32_t addr, uint32_t* f) {
    asm volatile("ldmatrix.sync.aligned.m8n8.x2.trans.shared.b16 {%0,%1}, [%2];"
                 : "=r"(f[0]), "=r"(f[1]) : "r"(addr));
}
__device__ __forceinline__ void mma_bf16(float* d, const uint32_t* a, const uint32_t* b) {
    asm volatile("mma.sync.aligned.m16n8k16.row.col.f32.bf16.bf16.f32 "
                 "{%0,%1,%2,%3}, {%4,%5,%6,%7}, {%8,%9}, {%0,%1,%2,%3};"
                 : "+f"(d[0]), "+f"(d[1]), "+f"(d[2]), "+f"(d[3])
                 : "r"(a[0]), "r"(a[1]), "r"(a[2]), "r"(a[3]),
                   "r"(b[0]), "r"(b[1]));
}

// ---------------------------------------------------------------------------
// Kernel 1: gate  gw[b,h,i,j] = max(g_row . W_g[:,h] + b_g[h], 1e-6)
// ---------------------------------------------------------------------------
__global__ __launch_bounds__(256) void gate_kernel(
    const float* __restrict__ G, const float* __restrict__ Wg,
    const float* __restrict__ bg, float* __restrict__ out)
{
    __shared__ float sW[64][16];
    __shared__ float sb[16];
    int tid = threadIdx.x;
    if (tid < 16) sb[tid] = bg[tid];
    for (int idx = tid; idx < 64 * 16; idx += 256)
        sW[idx >> 4][idx & 15] = Wg[idx];
    __syncthreads();

    int p = blockIdx.x * 256 + tid;
    const float4* g4 = (const float4*)(G + (size_t)p * 64);

    float acc[16];
#pragma unroll
    for (int h = 0; h < 16; h++) acc[h] = sb[h];

#pragma unroll
    for (int k4 = 0; k4 < 16; k4++) {
        float4 gv = g4[k4];
        float ge[4] = {gv.x, gv.y, gv.z, gv.w};
#pragma unroll
        for (int e = 0; e < 4; e++) {
            int k = 4 * k4 + e;
            float4 w0 = *(const float4*)&sW[k][0];
            float4 w1 = *(const float4*)&sW[k][4];
            float4 w2 = *(const float4*)&sW[k][8];
            float4 w3 = *(const float4*)&sW[k][12];
            acc[0]  += ge[e] * w0.x;  acc[1]  += ge[e] * w0.y;
            acc[2]  += ge[e] * w0.z;  acc[3]  += ge[e] * w0.w;
            acc[4]  += ge[e] * w1.x;  acc[5]  += ge[e] * w1.y;
            acc[6]  += ge[e] * w1.z;  acc[7]  += ge[e] * w1.w;
            acc[8]  += ge[e] * w2.x;  acc[9]  += ge[e] * w2.y;
            acc[10] += ge[e] * w2.z;  acc[11] += ge[e] * w2.w;
            acc[12] += ge[e] * w3.x;  acc[13] += ge[e] * w3.y;
            acc[14] += ge[e] * w3.z;  acc[15] += ge[e] * w3.w;
        }
    }

    int b  = p / (N_ * N_);
    int lp = p - b * (N_ * N_);
    float* ob = out + (size_t)b * (NR_ * N_ * N_) + lp;
#pragma unroll
    for (int h = 0; h < 16; h++)
        ob[(size_t)h * (N_ * N_)] = fmaxf(acc[h], 1e-6f);
}

// ---------------------------------------------------------------------------
// Kernel 2: fp32 -> bf16 hi/lo (elementwise; used for A, W_K, W_Q)
// ---------------------------------------------------------------------------
__global__ __launch_bounds__(256) void conv_kernel(const float* __restrict__ X,
                                                   __nv_bfloat16* __restrict__ hi,
                                                   __nv_bfloat16* __restrict__ lo)
{
    int i = (blockIdx.x * 256 + threadIdx.x) * 4;
    float4 v = *(const float4*)(X + i);
    float xs[4] = {v.x, v.y, v.z, v.w};
    __nv_bfloat16 h[4], l[4];
#pragma unroll
    for (int e = 0; e < 4; e++) {
        h[e] = __float2bfloat16(xs[e]);
        l[e] = __float2bfloat16(xs[e] - __bfloat162float(h[e]));
    }
    *(__nv_bfloat162*)(hi + i)     = __nv_bfloat162(h[0], h[1]);
    *(__nv_bfloat162*)(hi + i + 2) = __nv_bfloat162(h[2], h[3]);
    *(__nv_bfloat162*)(lo + i)     = __nv_bfloat162(l[0], l[1]);
    *(__nv_bfloat162*)(lo + i + 2) = __nv_bfloat162(l[2], l[3]);
}

// ---------------------------------------------------------------------------
// Kernel 3: bf16 3-pass GEMM via mma.sync.  C[6400,1024] = A@W + bias
// 128x128 CTA tile, 8 warps (2x4), warp tile 64x32, K-chunk 32,
// cp.async double buffering.  grid (8, 50, 2): z=0 -> K, z=1 -> Q.
//
// smem per buffer (32KB): Ahi[128][32] @0, Alo @8192, Whi[32][128] @16384,
// Wlo @24576.  A swizzle: off = r*64 + ((c ^ ((r>>1)&3))<<4), c = k-chunk(16B).
// W swizzle: off = k*256 + ((c ^ (k&7))<<4), c = n-chunk(16B).
// ---------------------------------------------------------------------------
#define KC 32
#define NCHUNKS (D_ / KC)        // 64
#define BUFBYTES 32768
#define GEMM_SMEM (2 * BUFBYTES)

__global__ __launch_bounds__(256, 1) void gemm_mma(
    const __nv_bfloat16* __restrict__ Ah, const __nv_bfloat16* __restrict__ Al,
    const __nv_bfloat16* __restrict__ WKh, const __nv_bfloat16* __restrict__ WKl,
    const __nv_bfloat16* __restrict__ WQh, const __nv_bfloat16* __restrict__ WQl,
    const float* __restrict__ bK, const float* __restrict__ bQ,
    float* __restrict__ gK, float* __restrict__ gQ)
{
    extern __shared__ char smem[];
    uint32_t sbase = smem_u32(smem);
    int tid = threadIdx.x;
    int wid = tid >> 5, lane = tid & 31;
    int wm = wid >> 2, wn = wid & 3;   // 2 x 4 warp grid

    const __nv_bfloat16 *Wh, *Wl;
    const float* bias;
    float* C;
    if (blockIdx.z == 0) { Wh = WKh; Wl = WKl; bias = bK; C = gK; }
    else                 { Wh = WQh; Wl = WQl; bias = bQ; C = gQ; }

    int m0 = blockIdx.y * 128;
    int n0 = blockIdx.x * 128;

    float acc[4][4][4];
#pragma unroll
    for (int mi = 0; mi < 4; mi++)
#pragma unroll
        for (int nj = 0; nj < 4; nj++)
#pragma unroll
            for (int e = 0; e < 4; e++) acc[mi][nj][e] = 0.f;

    // ---- async load of one K-chunk into buffer b ----
    auto load_chunk = [&](int c, int b) {
        int k0 = c * KC;
        uint32_t base = sbase + b * BUFBYTES;
        // A hi/lo: 128 rows x 32 k (64B rows), 512 chunks of 16B each
#pragma unroll
        for (int t = 0; t < 2; t++) {
            const __nv_bfloat16* src = t ? Al : Ah;
#pragma unroll
            for (int l2 = 0; l2 < 2; l2++) {
                int id = tid + l2 * 256;
                int r = id >> 2, cc = id & 3;
                cp_async16(base + t * 8192 + r * 64 + ((cc ^ ((r >> 1) & 3)) << 4),
                           src + (size_t)(m0 + r) * 2048 + k0 + cc * 8);
            }
        }
        // W hi/lo: 32 k-rows x 128 n (256B rows)
#pragma unroll
        for (int t = 0; t < 2; t++) {
            const __nv_bfloat16* src = t ? Wl : Wh;
#pragma unroll
            for (int l2 = 0; l2 < 2; l2++) {
                int id = tid + l2 * 256;
                int k = id >> 4, cc = id & 15;
                cp_async16(base + 16384 + t * 8192 + k * 256 + ((cc ^ (k & 7)) << 4),
                           src + (size_t)(k0 + k) * 1024 + n0 + cc * 8);
            }
        }
        CP_COMMIT();
    };

    load_chunk(0, 0);
    load_chunk(1, 1);

    // ldmatrix lane address components
    int ar  = (lane & 7) + ((lane >> 3) & 1) * 8;  // row within 16-row block (A)
    int acs = (lane >> 4) & 1;                     // k-chunk select (A)
    int bl  = lane & 15;
    int bk  = (bl & 7) + ((bl >> 3) & 1) * 8;      // k-row within k16 block (B)

    for (int c = 0; c < NCHUNKS; c++) {
        if (c == NCHUNKS - 1) { CP_WAIT(0); } else { CP_WAIT(1); }
        __syncthreads();
        uint32_t base = sbase + (c & 1) * BUFBYTES;

#pragma unroll
        for (int ki = 0; ki < 2; ki++) {
            uint32_t afh[4][4], afl[4][4];
#pragma unroll
            for (int mi = 0; mi < 4; mi++) {
                int r = wm * 64 + mi * 16 + ar;
                int chunk = ki * 2 + acs;
                uint32_t off = (uint32_t)(r * 64 + ((chunk ^ ((r >> 1) & 3)) << 4));
                ldsm_x4(base + off, afh[mi]);
                ldsm_x4(base + 8192 + off, afl[mi]);
            }
            uint32_t bfh[4][2], bfl[4][2];
#pragma unroll
            for (int nj = 0; nj < 4; nj++) {
                int k = ki * 16 + bk;
                int cc = wn * 4 + nj;
                uint32_t off = (uint32_t)(k * 256 + ((cc ^ (k & 7)) << 4));
                ldsm_x2t(base + 16384 + off, bfh[nj]);
                ldsm_x2t(base + 24576 + off, bfl[nj]);
            }
#pragma unroll
            for (int mi = 0; mi < 4; mi++)
#pragma unroll
                for (int nj = 0; nj < 4; nj++) {
                    mma_bf16(acc[mi][nj], afh[mi], bfh[nj]);
                    mma_bf16(acc[mi][nj], afh[mi], bfl[nj]);
                    mma_bf16(acc[mi][nj], afl[mi], bfh[nj]);
                }
        }
        __syncthreads();
        if (c + 2 < NCHUNKS) load_chunk(c + 2, c & 1);
    }

    // ---- epilogue: add bias, store fp32 ----
    int g = lane >> 2, t4 = lane & 3;
    float bcol[4][2];
#pragma unroll
    for (int nj = 0; nj < 4; nj++) {
        int col = n0 + wn * 32 + nj * 8 + t4 * 2;
        bcol[nj][0] = __ldg(bias + col);
        bcol[nj][1] = __ldg(bias + col + 1);
    }
#pragma unroll
    for (int mi = 0; mi < 4; mi++) {
#pragma unroll
        for (int half = 0; half < 2; half++) {
            int m = m0 + wm * 64 + mi * 16 + g + half * 8;
            float* crow = C + (size_t)m * 1024 + n0 + wn * 32;
#pragma unroll
            for (int nj = 0; nj < 4; nj++) {
                int col = nj * 8 + t4 * 2;
                float2 v;
                v.x = acc[mi][nj][half * 2 + 0] + bcol[nj][0];
                v.y = acc[mi][nj][half * 2 + 1] + bcol[nj][1];
                *(float2*)(crow + col) = v;
            }
        }
    }
}

// ---------------------------------------------------------------------------
// Kernel 4: per (b,h) attention
// ---------------------------------------------------------------------------
#define KQPAD 65
#define FINPAD 112

__global__ __launch_bounds__(256) void attn_kernel(
    const float* __restrict__ Kmat, const float* __restrict__ Qmat,
    const float* __restrict__ gw, const float* __restrict__ A,
    const float* __restrict__ wsp, const float* __restrict__ bsp,
    float* __restrict__ out)
{
    extern __shared__ float sm[];
    float* Ks  = sm;
    float* Qs  = sm + 112 * KQPAD;
    float* Vs  = sm;
    float* fin = sm + 2 * 112 * KQPAD;
    float* csum = fin + 100 * FINPAD;

    int h = blockIdx.x;
    int b = blockIdx.y;
    int tid = threadIdx.x;
    int tx = tid & 15, ty = tid >> 4;

    for (int idx = tid; idx < 112 * 64; idx += 256) {
        int i = idx >> 6, d = idx & 63;
        float kv = 0.f, qv = 0.f;
        if (i < 100) {
            size_t gofs = (size_t)(b * 100 + i) * 1024 + h * 64 + d;
            kv = Kmat[gofs];
            qv = Qmat[gofs];
        }
        Ks[i * KQPAD + d] = kv;
        Qs[i * KQPAD + d] = qv;
    }
    __syncthreads();

    const float* gwb = gw + ((size_t)(b * 16 + h)) * 10000;
    {
        float acc[7][7];
#pragma unroll
        for (int ii = 0; ii < 7; ii++)
#pragma unroll
            for (int jj = 0; jj < 7; jj++) acc[ii][jj] = 0.f;

        for (int d = 0; d < 64; d++) {
            float kk[7], qq[7];
#pragma unroll
            for (int ii = 0; ii < 7; ii++) kk[ii] = Ks[(ty + 16 * ii) * KQPAD + d];
#pragma unroll
            for (int jj = 0; jj < 7; jj++) qq[jj] = Qs[(tx + 16 * jj) * KQPAD + d];
#pragma unroll
            for (int ii = 0; ii < 7; ii++)
#pragma unroll
                for (int jj = 0; jj < 7; jj++)
                    acc[ii][jj] += kk[ii] * qq[jj];
        }
#pragma unroll
        for (int ii = 0; ii < 7; ii++) {
            int i = ty + 16 * ii;
            if (i >= 100) continue;
#pragma unroll
            for (int jj = 0; jj < 7; jj++) {
                int j = tx + 16 * jj;
                if (j >= 100) continue;
                float e = gwb[i * 100 + j] * __expf(acc[ii][jj] * 0.125f);
                fin[i * FINPAD + j] = e;
            }
        }
    }
    __syncthreads();

    if (tid < 100) {
        float s = 0.f;
        for (int i = 0; i < 100; i++) s += fin[i * FINPAD + tid];
        csum[tid] = 1.f / s;
    }
    for (int idx = tid; idx < 100 * 128; idx += 256) {
        int i = idx >> 7, d = idx & 127;
        Vs[idx] = A[(size_t)(b * 100 + i) * 2048 + h * 128 + d];
    }
    __syncthreads();

    float ws = wsp[0], bs = bsp[0];
    float r[7][8];
#pragma unroll
    for (int jj = 0; jj < 7; jj++)
#pragma unroll
        for (int dd = 0; dd < 8; dd++) r[jj][dd] = 0.f;

    for (int i = 0; i < 100; i++) {
        float vv[8], ff[7];
#pragma unroll
        for (int dd = 0; dd < 8; dd++) vv[dd] = Vs[i * 128 + tx + 16 * dd];
#pragma unroll
        for (int jj = 0; jj < 7; jj++) ff[jj] = fin[i * FINPAD + ty + 16 * jj];
#pragma unroll
        for (int jj = 0; jj < 7; jj++)
#pragma unroll
            for (int dd = 0; dd < 8; dd++)
                r[jj][dd] += vv[dd] * ff[jj];
    }

#pragma unroll
    for (int jj = 0; jj < 7; jj++) {
        int j = ty + 16 * jj;
        if (j >= 100) continue;
        float rc = csum[j];
        float* orow = out + (size_t)(b * 100 + j) * 2048 + h * 128;
#pragma unroll
        for (int dd = 0; dd < 8; dd++) {
            int d = tx + 16 * dd;
            orow[d] = (r[jj][dd] * rc) * ws + bs;
        }
    }
}

// ---------------------------------------------------------------------------
// Launcher
// ---------------------------------------------------------------------------
extern "C" void kernel_launch(void* const* d_in, const int* in_sizes, int n_in,
                              void* d_out, int out_size)
{
    const float* a_feat = (const float*)d_in[0];
    const float* g_feat = (const float*)d_in[1];
    const float* W_g    = (const float*)d_in[4];
    const float* b_g    = (const float*)d_in[5];
    const float* W_K    = (const float*)d_in[6];
    const float* b_K    = (const float*)d_in[7];
    const float* W_Q    = (const float*)d_in[8];
    const float* b_Q    = (const float*)d_in[9];
    const float* w_s    = (const float*)d_in[10];
    const float* b_s    = (const float*)d_in[11];
    float* out          = (float*)d_out;

    float *Kp, *Qp, *gwp;
    __nv_bfloat16 *Ahp, *Alp, *WKhp, *WKlp, *WQhp, *WQlp;
    cudaGetSymbolAddress((void**)&Kp,  g_K);
    cudaGetSymbolAddress((void**)&Qp,  g_Q);
    cudaGetSymbolAddress((void**)&gwp, g_gwT);
    cudaGetSymbolAddress((void**)&Ahp, g_Ahi);
    cudaGetSymbolAddress((void**)&Alp, g_Alo);
    cudaGetSymbolAddress((void**)&WKhp, g_WKhi);
    cudaGetSymbolAddress((void**)&WKlp, g_WKlo);
    cudaGetSymbolAddress((void**)&WQhp, g_WQhi);
    cudaGetSymbolAddress((void**)&WQlp, g_WQlo);

    // 1) fp32 -> bf16 hi/lo conversions (A, W_K, W_Q; W kept [k][n])
    conv_kernel<<<(P_ * D_) / 1024, 256>>>(a_feat, Ahp, Alp);
    conv_kernel<<<(D_ * KQ_COLS) / 1024, 256>>>(W_K, WKhp, WKlp);
    conv_kernel<<<(D_ * KQ_COLS) / 1024, 256>>>(W_Q, WQhp, WQlp);

    // 2) gate
    gate_kernel<<<PAIRS / 256, 256>>>(g_feat, W_g, b_g, gwp);

    // 3) K & Q GEMMs on tensor cores (mma.sync bf16, 3-pass split precision)
    cudaFuncSetAttribute(gemm_mma, cudaFuncAttributeMaxDynamicSharedMemorySize,
                         GEMM_SMEM);
    dim3 ggrid(KQ_COLS / 128, P_ / 128, 2);   // (8, 50, 2)
    gemm_mma<<<ggrid, 256, GEMM_SMEM>>>(Ahp, Alp, WKhp, WKlp, WQhp, WQlp,
                                        b_K, b_Q, Kp, Qp);

    // 4) attention + AV + affine
    int smem_bytes = (2 * 112 * KQPAD + 100 * FINPAD + 100) * (int)sizeof(float);
    cudaFuncSetAttribute(attn_kernel, cudaFuncAttributeMaxDynamicSharedMemorySize,
                         smem_bytes);
    dim3 agrid(NR_, B_);
    attn_kernel<<<agrid, 256, smem_bytes>>>(Kp, Qp, gwp, a_feat, w_s, b_s, out);
}

// round 5
// speedup vs baseline: 2.2249x; 1.1040x over previous
#include <cuda_runtime.h>
#include <cuda_bf16.h>
#include <cstdint>

// Problem constants
#define B_   64
#define N_   100
#define D_   2048
#define NR_  16
#define DK_  64
#define DV_  128
#define P_   (B_*N_)          // 6400
#define KQ_COLS (NR_*DK_)     // 1024
#define PAIRS (B_*N_*N_)      // 640000

// ---------------------------------------------------------------------------
// Scratch (device globals; allocation APIs are forbidden)
// ---------------------------------------------------------------------------
__device__ float g_K[P_ * KQ_COLS];          // 6400 x 1024
__device__ float g_Q[P_ * KQ_COLS];          // 6400 x 1024
__device__ float g_gwT[B_ * NR_ * N_ * N_];  // [b][h][i*100+j]

__device__ __align__(16) __nv_bfloat16 g_Ahi[P_ * D_];        // [m][k]
__device__ __align__(16) __nv_bfloat16 g_Alo[P_ * D_];
__device__ __align__(16) __nv_bfloat16 g_WKhi[D_ * KQ_COLS];  // [k][n]
__device__ __align__(16) __nv_bfloat16 g_WKlo[D_ * KQ_COLS];
__device__ __align__(16) __nv_bfloat16 g_WQhi[D_ * KQ_COLS];
__device__ __align__(16) __nv_bfloat16 g_WQlo[D_ * KQ_COLS];

// ---------------------------------------------------------------------------
// PTX helpers (baseline ISA only: cp.async / ldmatrix / mma.sync)
// ---------------------------------------------------------------------------
__device__ __forceinline__ uint32_t smem_u32(const void* p) {
    uint32_t a;
    asm("{ .reg .u64 t; cvta.to.shared.u64 t, %1; cvt.u32.u64 %0, t; }"
        : "=r"(a) : "l"(p));
    return a;
}
__device__ __forceinline__ void cp_async16(uint32_t dst, const void* src) {
    asm volatile("cp.async.cg.shared.global [%0], [%1], 16;" :: "r"(dst), "l"(src));
}
#define CP_COMMIT() asm volatile("cp.async.commit_group;" ::: "memory")
#define CP_WAIT(n)  asm volatile("cp.async.wait_group %0;" :: "n"(n) : "memory")

__device__ __forceinline__ void ldsm_x4(uint32_t addr, uint32_t* f) {
    asm volatile("ldmatrix.sync.aligned.m8n8.x4.shared.b16 {%0,%1,%2,%3}, [%4];"
                 : "=r"(f[0]), "=r"(f[1]), "=r"(f[2]), "=r"(f[3]) : "r"(addr));
}
__device__ __forceinline__ void ldsm_x4t(uint32_t addr, uint32_t* f) {
    asm volatile("ldmatrix.sync.aligned.m8n8.x4.trans.shared.b16 {%0,%1,%2,%3}, [%4];"
                 : "=r"(f[0]), "=r"(f[1]), "=r"(f[2]), "=r"(f[3]) : "r"(addr));
}
__device__ __forceinline__ void mma_bf16(float* d, const uint32_t* a, const uint32_t* b) {
    asm volatile("mma.sync.aligned.m16n8k16.row.col.f32.bf16.bf16.f32 "
                 "{%0,%1,%2,%3}, {%4,%5,%6,%7}, {%8,%9}, {%0,%1,%2,%3};"
                 : "+f"(d[0]), "+f"(d[1]), "+f"(d[2]), "+f"(d[3])
                 : "r"(a[0]), "r"(a[1]), "r"(a[2]), "r"(a[3]),
                   "r"(b[0]), "r"(b[1]));
}

// ---------------------------------------------------------------------------
// Kernel 1: gate.  4 pairs per thread: W smem tile read once per 4 pairs.
// ---------------------------------------------------------------------------
__global__ __launch_bounds__(256) void gate_kernel(
    const float* __restrict__ G, const float* __restrict__ Wg,
    const float* __restrict__ bg, float* __restrict__ out)
{
    __shared__ float sW[64][16];
    __shared__ float sb[16];
    int tid = threadIdx.x;
    if (tid < 16) sb[tid] = bg[tid];
    for (int idx = tid; idx < 64 * 16; idx += 256)
        sW[idx >> 4][idx & 15] = Wg[idx];
    __syncthreads();

    int p0 = blockIdx.x * 1024 + tid;     // pairs p0 + 256*q, q=0..3

    float acc[4][16];
#pragma unroll
    for (int q = 0; q < 4; q++)
#pragma unroll
        for (int h = 0; h < 16; h++) acc[q][h] = sb[h];

    const float4* g4 = (const float4*)(G + (size_t)p0 * 64);

#pragma unroll 4
    for (int k4 = 0; k4 < 16; k4++) {
        float4 gv[4];
#pragma unroll
        for (int q = 0; q < 4; q++)
            gv[q] = g4[q * (256 * 16) + k4];
#pragma unroll
        for (int e = 0; e < 4; e++) {
            int k = 4 * k4 + e;
            float4 w0 = *(const float4*)&sW[k][0];
            float4 w1 = *(const float4*)&sW[k][4];
            float4 w2 = *(const float4*)&sW[k][8];
            float4 w3 = *(const float4*)&sW[k][12];
            float wv[16] = {w0.x, w0.y, w0.z, w0.w, w1.x, w1.y, w1.z, w1.w,
                            w2.x, w2.y, w2.z, w2.w, w3.x, w3.y, w3.z, w3.w};
#pragma unroll
            for (int q = 0; q < 4; q++) {
                float ge = (e == 0) ? gv[q].x : (e == 1) ? gv[q].y
                         : (e == 2) ? gv[q].z : gv[q].w;
#pragma unroll
                for (int h = 0; h < 16; h++) acc[q][h] += ge * wv[h];
            }
        }
    }

#pragma unroll
    for (int q = 0; q < 4; q++) {
        int p  = p0 + q * 256;
        int b  = p / (N_ * N_);
        int lp = p - b * (N_ * N_);
        float* ob = out + (size_t)b * (NR_ * N_ * N_) + lp;
#pragma unroll
        for (int h = 0; h < 16; h++)
            ob[(size_t)h * (N_ * N_)] = fmaxf(acc[q][h], 1e-6f);
    }
}

// ---------------------------------------------------------------------------
// Kernel 2: fp32 -> bf16 hi/lo (elementwise; used for A, W_K, W_Q)
// ---------------------------------------------------------------------------
__global__ __launch_bounds__(256) void conv_kernel(const float* __restrict__ X,
                                                   __nv_bfloat16* __restrict__ hi,
                                                   __nv_bfloat16* __restrict__ lo)
{
    int i = (blockIdx.x * 256 + threadIdx.x) * 4;
    float4 v = *(const float4*)(X + i);
    float xs[4] = {v.x, v.y, v.z, v.w};
    __nv_bfloat16 h[4], l[4];
#pragma unroll
    for (int e = 0; e < 4; e++) {
        h[e] = __float2bfloat16(xs[e]);
        l[e] = __float2bfloat16(xs[e] - __bfloat162float(h[e]));
    }
    *(__nv_bfloat162*)(hi + i)     = __nv_bfloat162(h[0], h[1]);
    *(__nv_bfloat162*)(hi + i + 2) = __nv_bfloat162(h[2], h[3]);
    *(__nv_bfloat162*)(lo + i)     = __nv_bfloat162(l[0], l[1]);
    *(__nv_bfloat162*)(lo + i + 2) = __nv_bfloat162(l[2], l[3]);
}

// ---------------------------------------------------------------------------
// Kernel 3: bf16 3-pass GEMM via mma.sync.  C[6400,1024] = A@W + bias
// 128x128 CTA tile, 8 warps (2x4), warp tile 64x32, K-chunk 64,
// 3-stage cp.async pipeline (192KB smem).  grid (8, 50, 2): z=0->K, z=1->Q.
//
// stage layout (64KB): Ahi[128][64] @0, Alo @16384, Whi[64][128] @32768,
// Wlo @49152.
// A swizzle: off = r*128 + ((cc ^ (r&7))<<4), cc = 16B k-chunk 0..7.
// W swizzle: off = k*256 + ((cc ^ (k&7))<<4), cc = 16B n-chunk 0..15.
// ---------------------------------------------------------------------------
#define KC 64
#define NCHUNKS (D_ / KC)        // 32
#define STAGEBYTES 65536
#define GEMM_SMEM (3 * STAGEBYTES)

__global__ __launch_bounds__(256, 1) void gemm_mma(
    const __nv_bfloat16* __restrict__ Ah, const __nv_bfloat16* __restrict__ Al,
    const __nv_bfloat16* __restrict__ WKh, const __nv_bfloat16* __restrict__ WKl,
    const __nv_bfloat16* __restrict__ WQh, const __nv_bfloat16* __restrict__ WQl,
    const float* __restrict__ bK, const float* __restrict__ bQ,
    float* __restrict__ gK, float* __restrict__ gQ)
{
    extern __shared__ char smem[];
    uint32_t sbase = smem_u32(smem);
    int tid = threadIdx.x;
    int wid = tid >> 5, lane = tid & 31;
    int wm = wid >> 2, wn = wid & 3;   // 2 x 4 warp grid

    const __nv_bfloat16 *Wh, *Wl;
    const float* bias;
    float* C;
    if (blockIdx.z == 0) { Wh = WKh; Wl = WKl; bias = bK; C = gK; }
    else                 { Wh = WQh; Wl = WQl; bias = bQ; C = gQ; }

    int m0 = blockIdx.y * 128;
    int n0 = blockIdx.x * 128;

    float acc[4][4][4];
#pragma unroll
    for (int mi = 0; mi < 4; mi++)
#pragma unroll
        for (int nj = 0; nj < 4; nj++)
#pragma unroll
            for (int e = 0; e < 4; e++) acc[mi][nj][e] = 0.f;

    // ---- async load of one K-chunk into stage s ----
    auto load_chunk = [&](int c, int s) {
        int k0 = c * KC;
        uint32_t base = sbase + s * STAGEBYTES;
        // A hi/lo: 128 rows x 64 k = 128B rows, 1024 chunks of 16B each
#pragma unroll
        for (int t = 0; t < 2; t++) {
            const __nv_bfloat16* src = t ? Al : Ah;
#pragma unroll
            for (int l2 = 0; l2 < 4; l2++) {
                int id = tid + l2 * 256;        // 0..1023
                int r = id >> 3, cc = id & 7;
                cp_async16(base + t * 16384 + r * 128 + ((cc ^ (r & 7)) << 4),
                           src + (size_t)(m0 + r) * 2048 + k0 + cc * 8);
            }
        }
        // W hi/lo: 64 k-rows x 128 n = 256B rows, 1024 chunks
#pragma unroll
        for (int t = 0; t < 2; t++) {
            const __nv_bfloat16* src = t ? Wl : Wh;
#pragma unroll
            for (int l2 = 0; l2 < 4; l2++) {
                int id = tid + l2 * 256;
                int k = id >> 4, cc = id & 15;
                cp_async16(base + 32768 + t * 16384 + k * 256 + ((cc ^ (k & 7)) << 4),
                           src + (size_t)(k0 + k) * 1024 + n0 + cc * 8);
            }
        }
        CP_COMMIT();
    };

    load_chunk(0, 0);
    load_chunk(1, 1);
    load_chunk(2, 2);

    // ldmatrix lane address components
    int ar  = lane & 15;          // A: row within 16-row block
    int acs = lane >> 4;          // A: k16-half select (0/1)
    int wg8 = lane >> 3;          // W: 8-lane group 0..3
    int wk8 = lane & 7;           // W: k-row within 8
    int wks = (wg8 & 1) * 8;      // W: +8 k rows for odd groups
    int wns = wg8 >> 1;           // W: n-chunk select (0/1)

    int s = 0;
    for (int c = 0; c < NCHUNKS; c++) {
        CP_WAIT(2);
        __syncthreads();
        uint32_t base = sbase + s * STAGEBYTES;

#pragma unroll
        for (int ki = 0; ki < 4; ki++) {
            uint32_t afh[4][4], afl[4][4];
#pragma unroll
            for (int mi = 0; mi < 4; mi++) {
                int r = wm * 64 + mi * 16 + ar;
                int cc = 2 * ki + acs;
                uint32_t off = (uint32_t)(r * 128 + ((cc ^ (r & 7)) << 4));
                ldsm_x4(base + off, afh[mi]);
                ldsm_x4(base + 16384 + off, afl[mi]);
            }
            uint32_t bfh[4][2], bfl[4][2];
#pragma unroll
            for (int nh = 0; nh < 2; nh++) {
                int k  = ki * 16 + wks + wk8;
                int cc = wn * 4 + 2 * nh + wns;
                uint32_t off = (uint32_t)(k * 256 + ((cc ^ (k & 7)) << 4));
                uint32_t q[4];
                ldsm_x4t(base + 32768 + off, q);
                bfh[2 * nh][0] = q[0]; bfh[2 * nh][1] = q[1];
                bfh[2 * nh + 1][0] = q[2]; bfh[2 * nh + 1][1] = q[3];
                ldsm_x4t(base + 49152 + off, q);
                bfl[2 * nh][0] = q[0]; bfl[2 * nh][1] = q[1];
                bfl[2 * nh + 1][0] = q[2]; bfl[2 * nh + 1][1] = q[3];
            }
#pragma unroll
            for (int mi = 0; mi < 4; mi++)
#pragma unroll
                for (int nj = 0; nj < 4; nj++) {
                    mma_bf16(acc[mi][nj], afh[mi], bfh[nj]);
                    mma_bf16(acc[mi][nj], afh[mi], bfl[nj]);
                    mma_bf16(acc[mi][nj], afl[mi], bfh[nj]);
                }
        }
        __syncthreads();
        if (c + 3 < NCHUNKS) load_chunk(c + 3, s); else CP_COMMIT();
        s = (s == 2) ? 0 : s + 1;
    }

    // ---- epilogue: add bias, store fp32 ----
    int g = lane >> 2, t4 = lane & 3;
    float bcol[4][2];
#pragma unroll
    for (int nj = 0; nj < 4; nj++) {
        int col = n0 + wn * 32 + nj * 8 + t4 * 2;
        bcol[nj][0] = __ldg(bias + col);
        bcol[nj][1] = __ldg(bias + col + 1);
    }
#pragma unroll
    for (int mi = 0; mi < 4; mi++) {
#pragma unroll
        for (int half = 0; half < 2; half++) {
            int m = m0 + wm * 64 + mi * 16 + g + half * 8;
            float* crow = C + (size_t)m * 1024 + n0 + wn * 32;
#pragma unroll
            for (int nj = 0; nj < 4; nj++) {
                int col = nj * 8 + t4 * 2;
                float2 v;
                v.x = acc[mi][nj][half * 2 + 0] + bcol[nj][0];
                v.y = acc[mi][nj][half * 2 + 1] + bcol[nj][1];
                *(float2*)(crow + col) = v;
            }
        }
    }
}

// ---------------------------------------------------------------------------
// Kernel 4: per (b,h) attention
// ---------------------------------------------------------------------------
#define KQPAD 65
#define FINPAD 112

__global__ __launch_bounds__(256) void attn_kernel(
    const float* __restrict__ Kmat, const float* __restrict__ Qmat,
    const float* __restrict__ gw, const float* __restrict__ A,
    const float* __restrict__ wsp, const float* __restrict__ bsp,
    float* __restrict__ out)
{
    extern __shared__ float sm[];
    float* Ks  = sm;
    float* Qs  = sm + 112 * KQPAD;
    float* Vs  = sm;
    float* fin = sm + 2 * 112 * KQPAD;
    float* csum = fin + 100 * FINPAD;

    int h = blockIdx.x;
    int b = blockIdx.y;
    int tid = threadIdx.x;
    int tx = tid & 15, ty = tid >> 4;

    for (int idx = tid; idx < 112 * 64; idx += 256) {
        int i = idx >> 6, d = idx & 63;
        float kv = 0.f, qv = 0.f;
        if (i < 100) {
            size_t gofs = (size_t)(b * 100 + i) * 1024 + h * 64 + d;
            kv = Kmat[gofs];
            qv = Qmat[gofs];
        }
        Ks[i * KQPAD + d] = kv;
        Qs[i * KQPAD + d] = qv;
    }
    __syncthreads();

    const float* gwb = gw + ((size_t)(b * 16 + h)) * 10000;
    {
        float acc[7][7];
#pragma unroll
        for (int ii = 0; ii < 7; ii++)
#pragma unroll
            for (int jj = 0; jj < 7; jj++) acc[ii][jj] = 0.f;

        for (int d = 0; d < 64; d++) {
            float kk[7], qq[7];
#pragma unroll
            for (int ii = 0; ii < 7; ii++) kk[ii] = Ks[(ty + 16 * ii) * KQPAD + d];
#pragma unroll
            for (int jj = 0; jj < 7; jj++) qq[jj] = Qs[(tx + 16 * jj) * KQPAD + d];
#pragma unroll
            for (int ii = 0; ii < 7; ii++)
#pragma unroll
                for (int jj = 0; jj < 7; jj++)
                    acc[ii][jj] += kk[ii] * qq[jj];
        }
#pragma unroll
        for (int ii = 0; ii < 7; ii++) {
            int i = ty + 16 * ii;
            if (i >= 100) continue;
#pragma unroll
            for (int jj = 0; jj < 7; jj++) {
                int j = tx + 16 * jj;
                if (j >= 100) continue;
                float e = gwb[i * 100 + j] * __expf(acc[ii][jj] * 0.125f);
                fin[i * FINPAD + j] = e;
            }
        }
    }
    __syncthreads();

    if (tid < 100) {
        float ssum = 0.f;
        for (int i = 0; i < 100; i++) ssum += fin[i * FINPAD + tid];
        csum[tid] = 1.f / ssum;
    }
    for (int idx = tid; idx < 100 * 128; idx += 256) {
        int i = idx >> 7, d = idx & 127;
        Vs[idx] = A[(size_t)(b * 100 + i) * 2048 + h * 128 + d];
    }
    __syncthreads();

    float ws = wsp[0], bs = bsp[0];
    float r[7][8];
#pragma unroll
    for (int jj = 0; jj < 7; jj++)
#pragma unroll
        for (int dd = 0; dd < 8; dd++) r[jj][dd] = 0.f;

    for (int i = 0; i < 100; i++) {
        float vv[8], ff[7];
#pragma unroll
        for (int dd = 0; dd < 8; dd++) vv[dd] = Vs[i * 128 + tx + 16 * dd];
#pragma unroll
        for (int jj = 0; jj < 7; jj++) ff[jj] = fin[i * FINPAD + ty + 16 * jj];
#pragma unroll
        for (int jj = 0; jj < 7; jj++)
#pragma unroll
            for (int dd = 0; dd < 8; dd++)
                r[jj][dd] += vv[dd] * ff[jj];
    }

#pragma unroll
    for (int jj = 0; jj < 7; jj++) {
        int j = ty + 16 * jj;
        if (j >= 100) continue;
        float rc = csum[j];
        float* orow = out + (size_t)(b * 100 + j) * 2048 + h * 128;
#pragma unroll
        for (int dd = 0; dd < 8; dd++) {
            int d = tx + 16 * dd;
            orow[d] = (r[jj][dd] * rc) * ws + bs;
        }
    }
}

// ---------------------------------------------------------------------------
// Launcher
// ---------------------------------------------------------------------------
extern "C" void kernel_launch(void* const* d_in, const int* in_sizes, int n_in,
                              void* d_out, int out_size)
{
    const float* a_feat = (const float*)d_in[0];
    const float* g_feat = (const float*)d_in[1];
    const float* W_g    = (const float*)d_in[4];
    const float* b_g    = (const float*)d_in[5];
    const float* W_K    = (const float*)d_in[6];
    const float* b_K    = (const float*)d_in[7];
    const float* W_Q    = (const float*)d_in[8];
    const float* b_Q    = (const float*)d_in[9];
    const float* w_s    = (const float*)d_in[10];
    const float* b_s    = (const float*)d_in[11];
    float* out          = (float*)d_out;

    float *Kp, *Qp, *gwp;
    __nv_bfloat16 *Ahp, *Alp, *WKhp, *WKlp, *WQhp, *WQlp;
    cudaGetSymbolAddress((void**)&Kp,  g_K);
    cudaGetSymbolAddress((void**)&Qp,  g_Q);
    cudaGetSymbolAddress((void**)&gwp, g_gwT);
    cudaGetSymbolAddress((void**)&Ahp, g_Ahi);
    cudaGetSymbolAddress((void**)&Alp, g_Alo);
    cudaGetSymbolAddress((void**)&WKhp, g_WKhi);
    cudaGetSymbolAddress((void**)&WKlp, g_WKlo);
    cudaGetSymbolAddress((void**)&WQhp, g_WQhi);
    cudaGetSymbolAddress((void**)&WQlp, g_WQlo);

    // 1) fp32 -> bf16 hi/lo conversions
    conv_kernel<<<(P_ * D_) / 1024, 256>>>(a_feat, Ahp, Alp);
    conv_kernel<<<(D_ * KQ_COLS) / 1024, 256>>>(W_K, WKhp, WKlp);
    conv_kernel<<<(D_ * KQ_COLS) / 1024, 256>>>(W_Q, WQhp, WQlp);

    // 2) gate
    gate_kernel<<<PAIRS / 1024, 256>>>(g_feat, W_g, b_g, gwp);

    // 3) K & Q GEMMs (mma.sync bf16 3-pass, 3-stage pipeline)
    cudaFuncSetAttribute(gemm_mma, cudaFuncAttributeMaxDynamicSharedMemorySize,
                         GEMM_SMEM);
    dim3 ggrid(KQ_COLS / 128, P_ / 128, 2);   // (8, 50, 2)
    gemm_mma<<<ggrid, 256, GEMM_SMEM>>>(Ahp, Alp, WKhp, WKlp, WQhp, WQlp,
                                        b_K, b_Q, Kp, Qp);

    // 4) attention + AV + affine
    int smem_bytes = (2 * 112 * KQPAD + 100 * FINPAD + 100) * (int)sizeof(float);
    cudaFuncSetAttribute(attn_kernel, cudaFuncAttributeMaxDynamicSharedMemorySize,
                         smem_bytes);
    dim3 agrid(NR_, B_);
    attn_kernel<<<agrid, 256, smem_bytes>>>(Kp, Qp, gwp, a_feat, w_s, b_s, out);
}